// round 1
// baseline (speedup 1.0000x reference)
#include <cuda_runtime.h>
#include <math.h>

typedef unsigned long long ull;

// ---- geometry ----
#define NHEADS 16
#define DKDIM  32
#define DVDIM  16
#define CCH    256
#define TILE_M 32
#define NTHREADS 256

// per-voxel qkv smem layout (padded per head to kill bank conflicts)
#define QOFF 0
#define KOFF 528            // 16*33
#define VOFF 1056           // 528+528
#define VSTRIDE 1328        // 1056 + 16*17

#define SMT 36              // transposed-buffer row stride in floats (16B-aligned rows)
#define XT_OFF 0
#define R_OFF  (256*SMT)                  // 9216 : qkv region / attn_outT region
#define IT_OFF (R_OFF + 256*SMT)          // 18432 : interT region
#define SMEM_FLOATS (IT_OFF + 1024*SMT)   // 18432 + 36864 = 55296 floats = 216 KB

// ---- packed f32x2 helpers ----
__device__ __forceinline__ ull fma2(ull a, ull b, ull c) {
    ull d;
    asm("fma.rn.f32x2 %0, %1, %2, %3;" : "=l"(d) : "l"(a), "l"(b), "l"(c));
    return d;
}
__device__ __forceinline__ ull splat2(float f) {
    unsigned u = __float_as_uint(f);
    ull d;
    asm("mov.b64 %0, {%1, %1};" : "=l"(d) : "r"(u));
    return d;
}
__device__ __forceinline__ float2 unpack2(ull a) {
    unsigned lo, hi;
    asm("mov.b64 {%0, %1}, %2;" : "=r"(lo), "=r"(hi) : "l"(a));
    return make_float2(__uint_as_float(lo), __uint_as_float(hi));
}

// Y[32, 256-chunk] += A^T-tile @ W-chunk.
// sA: transposed A in smem, rows of SMT floats. Wp: W + colBase + tx*4 (row stride ldw).
// acc[mp][nt]: m-pair-packed accumulators; mp over 4 voxel-pairs, nt over 4 columns.
template<int K>
__device__ __forceinline__ void gemm_chunk(const float* __restrict__ Wp, int ldw,
                                           const float* sA, int aoff,
                                           ull acc[4][4]) {
#pragma unroll 8
    for (int c = 0; c < K; ++c) {
        const ulonglong2* xp = reinterpret_cast<const ulonglong2*>(sA + c * SMT + aoff);
        ulonglong2 xa = xp[0];          // m-pairs 0,1
        ulonglong2 xb = xp[1];          // m-pairs 2,3
        float4 w = *reinterpret_cast<const float4*>(Wp + (size_t)c * ldw);
        ull w0 = splat2(w.x), w1 = splat2(w.y), w2 = splat2(w.z), w3 = splat2(w.w);
        acc[0][0] = fma2(xa.x, w0, acc[0][0]);
        acc[1][0] = fma2(xa.y, w0, acc[1][0]);
        acc[2][0] = fma2(xb.x, w0, acc[2][0]);
        acc[3][0] = fma2(xb.y, w0, acc[3][0]);
        acc[0][1] = fma2(xa.x, w1, acc[0][1]);
        acc[1][1] = fma2(xa.y, w1, acc[1][1]);
        acc[2][1] = fma2(xb.x, w1, acc[2][1]);
        acc[3][1] = fma2(xb.y, w1, acc[3][1]);
        acc[0][2] = fma2(xa.x, w2, acc[0][2]);
        acc[1][2] = fma2(xa.y, w2, acc[1][2]);
        acc[2][2] = fma2(xb.x, w2, acc[2][2]);
        acc[3][2] = fma2(xb.y, w2, acc[3][2]);
        acc[0][3] = fma2(xa.x, w3, acc[0][3]);
        acc[1][3] = fma2(xa.y, w3, acc[1][3]);
        acc[2][3] = fma2(xb.x, w3, acc[2][3]);
        acc[3][3] = fma2(xb.y, w3, acc[3][3]);
    }
}

__device__ __forceinline__ void zero_acc(ull acc[4][4]) {
#pragma unroll
    for (int i = 0; i < 4; ++i)
#pragma unroll
        for (int j = 0; j < 4; ++j) acc[i][j] = 0ULL;
}

// scatter a qkv GEMM chunk into the per-voxel padded layout (+bias)
__device__ __forceinline__ void store_qkv(float* sR, ull acc[4][4], int mg, int j,
                                          const float* __restrict__ bias,
                                          int partBase, int hshift, int hstride) {
#pragma unroll
    for (int nt = 0; nt < 4; ++nt) {
        int n = j + nt;
        float b = bias[n];
        int off = partBase + (n >> hshift) * hstride + (n & ((1 << hshift) - 1));
#pragma unroll
        for (int mp = 0; mp < 4; ++mp) {
            float2 v = unpack2(acc[mp][nt]);
            int m0 = mg * 8 + mp * 2;
            sR[m0 * VSTRIDE + off]       = v.x + b;
            sR[(m0 + 1) * VSTRIDE + off] = v.y + b;
        }
    }
}

__global__ void __launch_bounds__(NTHREADS, 1)
msa_block_kernel(const float* __restrict__ x,
                 const float* __restrict__ Wq, const float* __restrict__ bq,
                 const float* __restrict__ Wk, const float* __restrict__ bk,
                 const float* __restrict__ Wv, const float* __restrict__ bv,
                 const float* __restrict__ W1, const float* __restrict__ b1,
                 const float* __restrict__ Wo, const float* __restrict__ bo,
                 const float* __restrict__ Wc, const float* __restrict__ bc,
                 const float* __restrict__ gamma, const float* __restrict__ beta,
                 const float* __restrict__ mu, const float* __restrict__ var,
                 float* __restrict__ out) {
    extern __shared__ float sm[];
    float* sXT = sm;               // [256][SMT] x transposed
    float* sR  = sm + R_OFF;       // qkv region, later attn_outT [256][SMT]
    float* sIT = sm + IT_OFF;      // interT [1024][SMT]

    const int t  = threadIdx.x;
    const int tx = t & 63;
    const int mg = t >> 6;
    const int aoff = mg * 8;
    const long long vb = (long long)blockIdx.x * TILE_M;

    // ---- load x tile, transposed into smem ----
    {
        const float4* xg = reinterpret_cast<const float4*>(x + vb * CCH);
#pragma unroll
        for (int i = 0; i < 8; ++i) {
            int idx4 = i * NTHREADS + t;       // 2048 float4s = 32*256 floats
            float4 v = xg[idx4];
            int m = (idx4 * 4) >> 8;
            int c = (idx4 * 4) & 255;
            sXT[(c + 0) * SMT + m] = v.x;
            sXT[(c + 1) * SMT + m] = v.y;
            sXT[(c + 2) * SMT + m] = v.z;
            sXT[(c + 3) * SMT + m] = v.w;
        }
    }
    __syncthreads();

    // ---- stage 1: QKV projections into padded per-voxel layout ----
    {
        ull acc[4][4];
#pragma unroll 1
        for (int cb = 0; cb < 512; cb += 256) {   // Q
            zero_acc(acc);
            gemm_chunk<256>(Wq + cb + tx * 4, 512, sXT, aoff, acc);
            store_qkv(sR, acc, mg, cb + tx * 4, bq, QOFF, 5, 33);
        }
#pragma unroll 1
        for (int cb = 0; cb < 512; cb += 256) {   // K
            zero_acc(acc);
            gemm_chunk<256>(Wk + cb + tx * 4, 512, sXT, aoff, acc);
            store_qkv(sR, acc, mg, cb + tx * 4, bk, KOFF, 5, 33);
        }
        {                                          // V
            zero_acc(acc);
            gemm_chunk<256>(Wv + tx * 4, 256, sXT, aoff, acc);
            store_qkv(sR, acc, mg, tx * 4, bv, VOFF, 4, 17);
        }
    }
    __syncthreads();

    // ---- stage 2: per-voxel head attention (16x16 scores, softmax, AV) ----
    float outr[2][DVDIM];
#pragma unroll
    for (int pi = 0; pi < 2; ++pi) {
        int p = t + pi * NTHREADS;      // 512 (voxel, head) pairs
        int m = p >> 4, h = p & 15;
        const float* vox = sR + m * VSTRIDE;
        const float* qh  = vox + h * 33;
        float sc[NHEADS];
        float mx = -1e30f;
#pragma unroll
        for (int g = 0; g < NHEADS; ++g) {
            const float* kg = vox + KOFF + g * 33;
            float s = 0.f;
#pragma unroll
            for (int d = 0; d < DKDIM; ++d) s = fmaf(qh[d], kg[d], s);
            s *= 0.17677669529663689f;   // 1/sqrt(32)
            sc[g] = s;
            mx = fmaxf(mx, s);
        }
        float sum = 0.f;
#pragma unroll
        for (int g = 0; g < NHEADS; ++g) { sc[g] = __expf(sc[g] - mx); sum += sc[g]; }
        float inv = 1.f / sum;
#pragma unroll
        for (int dv = 0; dv < DVDIM; ++dv) outr[pi][dv] = 0.f;
#pragma unroll
        for (int g = 0; g < NHEADS; ++g) {
            float pg = sc[g] * inv;
            const float* vg = vox + VOFF + g * 17;
#pragma unroll
            for (int dv = 0; dv < DVDIM; ++dv)
                outr[pi][dv] = fmaf(pg, vg[dv], outr[pi][dv]);
        }
    }
    __syncthreads();
    // write attn_out transposed over the (dead) q region
#pragma unroll
    for (int pi = 0; pi < 2; ++pi) {
        int p = t + pi * NTHREADS;
        int m = p >> 4, h = p & 15;
#pragma unroll
        for (int dv = 0; dv < DVDIM; ++dv)
            sR[(h * DVDIM + dv) * SMT + m] = outr[pi][dv];
    }
    __syncthreads();

    // ---- stage 3: FFN up-proj (relu), stored transposed ----
    {
        ull acc[4][4];
#pragma unroll 1
        for (int cb = 0; cb < 1024; cb += 256) {
            zero_acc(acc);
            gemm_chunk<256>(W1 + cb + tx * 4, 1024, sR /*attn_outT*/, aoff, acc);
            int j = cb + tx * 4;
#pragma unroll
            for (int nt = 0; nt < 4; ++nt) {
                int n = j + nt;
                float b = b1[n];
                float2 a0 = unpack2(acc[0][nt]);
                float2 a1 = unpack2(acc[1][nt]);
                float2 a2 = unpack2(acc[2][nt]);
                float2 a3 = unpack2(acc[3][nt]);
                float4 lo = make_float4(fmaxf(a0.x + b, 0.f), fmaxf(a0.y + b, 0.f),
                                        fmaxf(a1.x + b, 0.f), fmaxf(a1.y + b, 0.f));
                float4 hi = make_float4(fmaxf(a2.x + b, 0.f), fmaxf(a2.y + b, 0.f),
                                        fmaxf(a3.x + b, 0.f), fmaxf(a3.y + b, 0.f));
                *reinterpret_cast<float4*>(sIT + n * SMT + aoff)     = lo;
                *reinterpret_cast<float4*>(sIT + n * SMT + aoff + 4) = hi;
            }
        }
    }
    __syncthreads();

    // ---- stage 4: residual conv (relu) + FFN down-proj + batchnorm ----
    {
        ull accR[4][4];
        zero_acc(accR);
        gemm_chunk<256>(Wc + tx * 4, 256, sXT, aoff, accR);
        ull accO[4][4];
        zero_acc(accO);
        gemm_chunk<1024>(Wo + tx * 4, 256, sIT, aoff, accO);

        int j = tx * 4;
        float bcv[4], bov[4], muv[4], sv[4], bev[4];
#pragma unroll
        for (int nt = 0; nt < 4; ++nt) {
            int n = j + nt;
            bcv[nt] = bc[n];
            bov[nt] = bo[n];
            muv[nt] = mu[n];
            sv[nt]  = gamma[n] * rsqrtf(var[n] + 1e-6f);
            bev[nt] = beta[n];
        }
#pragma unroll
        for (int mp = 0; mp < 4; ++mp) {
            float ylo[4], yhi[4];
#pragma unroll
            for (int nt = 0; nt < 4; ++nt) {
                float2 r = unpack2(accR[mp][nt]);
                float2 o = unpack2(accO[mp][nt]);
                ylo[nt] = (fmaxf(r.x + bcv[nt], 0.f) + o.x + bov[nt] - muv[nt]) * sv[nt] + bev[nt];
                yhi[nt] = (fmaxf(r.y + bcv[nt], 0.f) + o.y + bov[nt] - muv[nt]) * sv[nt] + bev[nt];
            }
            long long m0 = vb + mg * 8 + mp * 2;
            *reinterpret_cast<float4*>(out + m0 * CCH + j)       = make_float4(ylo[0], ylo[1], ylo[2], ylo[3]);
            *reinterpret_cast<float4*>(out + (m0 + 1) * CCH + j) = make_float4(yhi[0], yhi[1], yhi[2], yhi[3]);
        }
    }
}

extern "C" void kernel_launch(void* const* d_in, const int* in_sizes, int n_in,
                              void* d_out, int out_size) {
    const float* x     = (const float*)d_in[0];
    const float* Wq    = (const float*)d_in[1];
    const float* bq    = (const float*)d_in[2];
    const float* Wk    = (const float*)d_in[3];
    const float* bk    = (const float*)d_in[4];
    const float* Wv    = (const float*)d_in[5];
    const float* bv    = (const float*)d_in[6];
    const float* W1    = (const float*)d_in[7];
    const float* b1    = (const float*)d_in[8];
    const float* Wo    = (const float*)d_in[9];
    const float* bo    = (const float*)d_in[10];
    const float* Wc    = (const float*)d_in[11];
    const float* bc    = (const float*)d_in[12];
    const float* gamma = (const float*)d_in[13];
    const float* beta  = (const float*)d_in[14];
    const float* mu    = (const float*)d_in[15];
    const float* var   = (const float*)d_in[16];
    float* out = (float*)d_out;

    int nvox = in_sizes[0] / CCH;               // 131072
    int nblocks = nvox / TILE_M;                // 4096
    size_t smem = SMEM_FLOATS * sizeof(float);  // 221184 bytes

    cudaFuncSetAttribute(msa_block_kernel,
                         cudaFuncAttributeMaxDynamicSharedMemorySize, (int)smem);
    msa_block_kernel<<<nblocks, NTHREADS, smem>>>(
        x, Wq, bq, Wk, bk, Wv, bv, W1, b1, Wo, bo, Wc, bc,
        gamma, beta, mu, var, out);
}

// round 4
// speedup vs baseline: 1.0017x; 1.0017x over previous
#include <cuda_runtime.h>
#include <math.h>

typedef unsigned long long ull;

// ---- geometry ----
#define NHEADS 16
#define DKDIM  32
#define DVDIM  16
#define CCH    256
#define TILE_M 32
#define NTHREADS 256

// per-voxel qkv smem layout (padded per head to kill bank conflicts)
#define QOFF 0
#define KOFF 528            // 16*33
#define VOFF 1056           // 528+528
#define VSTRIDE 1328        // 1056 + 16*17

#define SMT 36              // transposed-buffer row stride in floats (16B-aligned rows)
#define XT_OFF 0
#define R_OFF  (256*SMT)                  // 9216 : qkv region / attn_outT region
#define IT_OFF (R_OFF + 256*SMT)          // 18432 : interT region
#define SMEM_FLOATS (IT_OFF + 1024*SMT)   // 18432 + 36864 = 55296 floats = 216 KB

// ---- packed f32x2 helpers ----
__device__ __forceinline__ ull fma2(ull a, ull b, ull c) {
    ull d;
    asm("fma.rn.f32x2 %0, %1, %2, %3;" : "=l"(d) : "l"(a), "l"(b), "l"(c));
    return d;
}
__device__ __forceinline__ ull splat2(float f) {
    unsigned u = __float_as_uint(f);
    ull d;
    asm("mov.b64 %0, {%1, %1};" : "=l"(d) : "r"(u));
    return d;
}
__device__ __forceinline__ float2 unpack2(ull a) {
    unsigned lo, hi;
    asm("mov.b64 {%0, %1}, %2;" : "=r"(lo), "=r"(hi) : "l"(a));
    return make_float2(__uint_as_float(lo), __uint_as_float(hi));
}

// Y[32, 256-chunk] += A^T-tile @ W-chunk.
// sA: transposed A in smem, rows of SMT floats. Wp: W + colBase + tx*4 (row stride ldw).
// acc[mp][nt]: m-pair-packed accumulators; mp over 4 voxel-pairs, nt over 4 columns.
template<int K>
__device__ __forceinline__ void gemm_chunk(const float* __restrict__ Wp, int ldw,
                                           const float* sA, int aoff,
                                           ull acc[4][4]) {
#pragma unroll 8
    for (int c = 0; c < K; ++c) {
        const ulonglong2* xp = reinterpret_cast<const ulonglong2*>(sA + c * SMT + aoff);
        ulonglong2 xa = xp[0];          // m-pairs 0,1
        ulonglong2 xb = xp[1];          // m-pairs 2,3
        float4 w = *reinterpret_cast<const float4*>(Wp + (size_t)c * ldw);
        ull w0 = splat2(w.x), w1 = splat2(w.y), w2 = splat2(w.z), w3 = splat2(w.w);
        acc[0][0] = fma2(xa.x, w0, acc[0][0]);
        acc[1][0] = fma2(xa.y, w0, acc[1][0]);
        acc[2][0] = fma2(xb.x, w0, acc[2][0]);
        acc[3][0] = fma2(xb.y, w0, acc[3][0]);
        acc[0][1] = fma2(xa.x, w1, acc[0][1]);
        acc[1][1] = fma2(xa.y, w1, acc[1][1]);
        acc[2][1] = fma2(xb.x, w1, acc[2][1]);
        acc[3][1] = fma2(xb.y, w1, acc[3][1]);
        acc[0][2] = fma2(xa.x, w2, acc[0][2]);
        acc[1][2] = fma2(xa.y, w2, acc[1][2]);
        acc[2][2] = fma2(xb.x, w2, acc[2][2]);
        acc[3][2] = fma2(xb.y, w2, acc[3][2]);
        acc[0][3] = fma2(xa.x, w3, acc[0][3]);
        acc[1][3] = fma2(xa.y, w3, acc[1][3]);
        acc[2][3] = fma2(xb.x, w3, acc[2][3]);
        acc[3][3] = fma2(xb.y, w3, acc[3][3]);
    }
}

__device__ __forceinline__ void zero_acc(ull acc[4][4]) {
#pragma unroll
    for (int i = 0; i < 4; ++i)
#pragma unroll
        for (int j = 0; j < 4; ++j) acc[i][j] = 0ULL;
}

// scatter a qkv GEMM chunk into the per-voxel padded layout (+bias)
__device__ __forceinline__ void store_qkv(float* sR, ull acc[4][4], int mg, int j,
                                          const float* __restrict__ bias,
                                          int partBase, int hshift, int hstride) {
#pragma unroll
    for (int nt = 0; nt < 4; ++nt) {
        int n = j + nt;
        float b = bias[n];
        int off = partBase + (n >> hshift) * hstride + (n & ((1 << hshift) - 1));
#pragma unroll
        for (int mp = 0; mp < 4; ++mp) {
            float2 v = unpack2(acc[mp][nt]);
            int m0 = mg * 8 + mp * 2;
            sR[m0 * VSTRIDE + off]       = v.x + b;
            sR[(m0 + 1) * VSTRIDE + off] = v.y + b;
        }
    }
}

__global__ void __launch_bounds__(NTHREADS, 1)
msa_block_kernel(const float* __restrict__ x,
                 const float* __restrict__ Wq, const float* __restrict__ bq,
                 const float* __restrict__ Wk, const float* __restrict__ bk,
                 const float* __restrict__ Wv, const float* __restrict__ bv,
                 const float* __restrict__ W1, const float* __restrict__ b1,
                 const float* __restrict__ Wo, const float* __restrict__ bo,
                 const float* __restrict__ Wc, const float* __restrict__ bc,
                 const float* __restrict__ gamma, const float* __restrict__ beta,
                 const float* __restrict__ mu, const float* __restrict__ var,
                 float* __restrict__ out) {
    extern __shared__ float sm[];
    float* sXT = sm;               // [256][SMT] x transposed
    float* sR  = sm + R_OFF;       // qkv region, later attn_outT [256][SMT]
    float* sIT = sm + IT_OFF;      // interT [1024][SMT]

    const int t  = threadIdx.x;
    const int tx = t & 63;
    const int mg = t >> 6;
    const int aoff = mg * 8;
    const long long vb = (long long)blockIdx.x * TILE_M;

    // ---- load x tile, transposed into smem ----
    {
        const float4* xg = reinterpret_cast<const float4*>(x + vb * CCH);
#pragma unroll
        for (int i = 0; i < 8; ++i) {
            int idx4 = i * NTHREADS + t;       // 2048 float4s = 32*256 floats
            float4 v = xg[idx4];
            int m = (idx4 * 4) >> 8;
            int c = (idx4 * 4) & 255;
            sXT[(c + 0) * SMT + m] = v.x;
            sXT[(c + 1) * SMT + m] = v.y;
            sXT[(c + 2) * SMT + m] = v.z;
            sXT[(c + 3) * SMT + m] = v.w;
        }
    }
    __syncthreads();

    // ---- stage 1: QKV projections into padded per-voxel layout ----
    {
        ull acc[4][4];
#pragma unroll 1
        for (int cb = 0; cb < 512; cb += 256) {   // Q
            zero_acc(acc);
            gemm_chunk<256>(Wq + cb + tx * 4, 512, sXT, aoff, acc);
            store_qkv(sR, acc, mg, cb + tx * 4, bq, QOFF, 5, 33);
        }
#pragma unroll 1
        for (int cb = 0; cb < 512; cb += 256) {   // K
            zero_acc(acc);
            gemm_chunk<256>(Wk + cb + tx * 4, 512, sXT, aoff, acc);
            store_qkv(sR, acc, mg, cb + tx * 4, bk, KOFF, 5, 33);
        }
        {                                          // V
            zero_acc(acc);
            gemm_chunk<256>(Wv + tx * 4, 256, sXT, aoff, acc);
            store_qkv(sR, acc, mg, tx * 4, bv, VOFF, 4, 17);
        }
    }
    __syncthreads();

    // ---- stage 2: per-voxel head attention (16x16 scores, softmax, AV) ----
    float outr[2][DVDIM];
#pragma unroll
    for (int pi = 0; pi < 2; ++pi) {
        int p = t + pi * NTHREADS;      // 512 (voxel, head) pairs
        int m = p >> 4, h = p & 15;
        const float* vox = sR + m * VSTRIDE;
        const float* qh  = vox + h * 33;
        float sc[NHEADS];
        float mx = -1e30f;
#pragma unroll
        for (int g = 0; g < NHEADS; ++g) {
            const float* kg = vox + KOFF + g * 33;
            float s = 0.f;
#pragma unroll
            for (int d = 0; d < DKDIM; ++d) s = fmaf(qh[d], kg[d], s);
            s *= 0.17677669529663689f;   // 1/sqrt(32)
            sc[g] = s;
            mx = fmaxf(mx, s);
        }
        float sum = 0.f;
#pragma unroll
        for (int g = 0; g < NHEADS; ++g) { sc[g] = __expf(sc[g] - mx); sum += sc[g]; }
        float inv = 1.f / sum;
#pragma unroll
        for (int dv = 0; dv < DVDIM; ++dv) outr[pi][dv] = 0.f;
#pragma unroll
        for (int g = 0; g < NHEADS; ++g) {
            float pg = sc[g] * inv;
            const float* vg = vox + VOFF + g * 17;
#pragma unroll
            for (int dv = 0; dv < DVDIM; ++dv)
                outr[pi][dv] = fmaf(pg, vg[dv], outr[pi][dv]);
        }
    }
    __syncthreads();
    // write attn_out transposed over the (dead) q region
#pragma unroll
    for (int pi = 0; pi < 2; ++pi) {
        int p = t + pi * NTHREADS;
        int m = p >> 4, h = p & 15;
#pragma unroll
        for (int dv = 0; dv < DVDIM; ++dv)
            sR[(h * DVDIM + dv) * SMT + m] = outr[pi][dv];
    }
    __syncthreads();

    // ---- stage 3: FFN up-proj (relu), stored transposed ----
    {
        ull acc[4][4];
#pragma unroll 1
        for (int cb = 0; cb < 1024; cb += 256) {
            zero_acc(acc);
            gemm_chunk<256>(W1 + cb + tx * 4, 1024, sR /*attn_outT*/, aoff, acc);
            int j = cb + tx * 4;
#pragma unroll
            for (int nt = 0; nt < 4; ++nt) {
                int n = j + nt;
                float b = b1[n];
                float2 a0 = unpack2(acc[0][nt]);
                float2 a1 = unpack2(acc[1][nt]);
                float2 a2 = unpack2(acc[2][nt]);
                float2 a3 = unpack2(acc[3][nt]);
                float4 lo = make_float4(fmaxf(a0.x + b, 0.f), fmaxf(a0.y + b, 0.f),
                                        fmaxf(a1.x + b, 0.f), fmaxf(a1.y + b, 0.f));
                float4 hi = make_float4(fmaxf(a2.x + b, 0.f), fmaxf(a2.y + b, 0.f),
                                        fmaxf(a3.x + b, 0.f), fmaxf(a3.y + b, 0.f));
                *reinterpret_cast<float4*>(sIT + n * SMT + aoff)     = lo;
                *reinterpret_cast<float4*>(sIT + n * SMT + aoff + 4) = hi;
            }
        }
    }
    __syncthreads();

    // ---- stage 4: residual conv (relu) + FFN down-proj + batchnorm ----
    {
        ull accR[4][4];
        zero_acc(accR);
        gemm_chunk<256>(Wc + tx * 4, 256, sXT, aoff, accR);
        ull accO[4][4];
        zero_acc(accO);
        gemm_chunk<1024>(Wo + tx * 4, 256, sIT, aoff, accO);

        int j = tx * 4;
        float bcv[4], bov[4], muv[4], sv[4], bev[4];
#pragma unroll
        for (int nt = 0; nt < 4; ++nt) {
            int n = j + nt;
            bcv[nt] = bc[n];
            bov[nt] = bo[n];
            muv[nt] = mu[n];
            sv[nt]  = gamma[n] * rsqrtf(var[n] + 1e-6f);
            bev[nt] = beta[n];
        }
#pragma unroll
        for (int mp = 0; mp < 4; ++mp) {
            float ylo[4], yhi[4];
#pragma unroll
            for (int nt = 0; nt < 4; ++nt) {
                float2 r = unpack2(accR[mp][nt]);
                float2 o = unpack2(accO[mp][nt]);
                ylo[nt] = (fmaxf(r.x + bcv[nt], 0.f) + o.x + bov[nt] - muv[nt]) * sv[nt] + bev[nt];
                yhi[nt] = (fmaxf(r.y + bcv[nt], 0.f) + o.y + bov[nt] - muv[nt]) * sv[nt] + bev[nt];
            }
            long long m0 = vb + mg * 8 + mp * 2;
            *reinterpret_cast<float4*>(out + m0 * CCH + j)       = make_float4(ylo[0], ylo[1], ylo[2], ylo[3]);
            *reinterpret_cast<float4*>(out + (m0 + 1) * CCH + j) = make_float4(yhi[0], yhi[1], yhi[2], yhi[3]);
        }
    }
}

extern "C" void kernel_launch(void* const* d_in, const int* in_sizes, int n_in,
                              void* d_out, int out_size) {
    const float* x     = (const float*)d_in[0];
    const float* Wq    = (const float*)d_in[1];
    const float* bq    = (const float*)d_in[2];
    const float* Wk    = (const float*)d_in[3];
    const float* bk    = (const float*)d_in[4];
    const float* Wv    = (const float*)d_in[5];
    const float* bv    = (const float*)d_in[6];
    const float* W1    = (const float*)d_in[7];
    const float* b1    = (const float*)d_in[8];
    const float* Wo    = (const float*)d_in[9];
    const float* bo    = (const float*)d_in[10];
    const float* Wc    = (const float*)d_in[11];
    const float* bc    = (const float*)d_in[12];
    const float* gamma = (const float*)d_in[13];
    const float* beta  = (const float*)d_in[14];
    const float* mu    = (const float*)d_in[15];
    const float* var   = (const float*)d_in[16];
    float* out = (float*)d_out;

    int nvox = in_sizes[0] / CCH;               // 131072
    int nblocks = nvox / TILE_M;                // 4096
    size_t smem = SMEM_FLOATS * sizeof(float);  // 221184 bytes

    cudaFuncSetAttribute(msa_block_kernel,
                         cudaFuncAttributeMaxDynamicSharedMemorySize, (int)smem);
    msa_block_kernel<<<nblocks, NTHREADS, smem>>>(
        x, Wq, bq, Wk, bk, Wv, bv, W1, b1, Wo, bo, Wc, bc,
        gamma, beta, mu, var, out);
}